// round 15
// baseline (speedup 1.0000x reference)
#include <cuda_runtime.h>
#include <cuda.h>
#include <cuda_bf16.h>
#include <float.h>
#include <cstdint>

// Problem constants
#define BB 32
#define SS 2048
#define DD 1024
#define EE 16
#define KK 4
#define OO 1024
#define KD 4096   // KK*DD
#define SPLIT 4

typedef unsigned long long ULL;

// ---------------- scratch (device globals) ----------------
__device__ float g_logits[BB * EE * SS];            // [B][E][S], 4 MB
__device__ float g_wgt[EE * DD];                    // Wg transposed [e][k], 64 KB
__device__ __nv_bfloat16 g_inph[EE * BB * KD];      // inp hi, [e][b][4096]
__device__ __nv_bfloat16 g_inpl[EE * BB * KD];      // inp lo
__device__ __nv_bfloat16 g_h1h[EE * BB * OO];
__device__ __nv_bfloat16 g_h1l[EE * BB * OO];
__device__ __nv_bfloat16 g_h2h[EE * BB * OO];
__device__ __nv_bfloat16 g_h2l[EE * BB * OO];
__device__ float g_part[SPLIT * EE * BB * OO];      // split-K partials (GEMM1), 8 MB

// ---------------- f32x2 helpers ----------------
__device__ __forceinline__ void fma2(ULL& d, ULL a, ULL b) {
    asm("fma.rn.f32x2 %0, %1, %2, %0;" : "+l"(d) : "l"(a), "l"(b));
}
__device__ __forceinline__ float2 unpack2(ULL v) {
    float2 f; asm("mov.b64 {%0, %1}, %2;" : "=f"(f.x), "=f"(f.y) : "l"(v)); return f;
}

// ---------------- bf16 split helper ----------------
__device__ __forceinline__ void split2(float a, float b, uint32_t& hi, uint32_t& lo) {
    asm("cvt.rn.satfinite.bf16x2.f32 %0, %1, %2;" : "=r"(hi) : "f"(b), "f"(a));
    __nv_bfloat162 hp = *reinterpret_cast<__nv_bfloat162*>(&hi);
    float r0 = a - __low2float(hp);
    float r1 = b - __high2float(hp);
    asm("cvt.rn.satfinite.bf16x2.f32 %0, %1, %2;" : "=r"(lo) : "f"(r1), "f"(r0));
}

// ---------------- portable tensor-core / TMA helpers ----------------
__device__ __forceinline__ uint32_t smem_u32(const void* p) {
    uint32_t a;
    asm("{ .reg .u64 t; cvta.to.shared.u64 t, %1; cvt.u32.u64 %0, t; }" : "=r"(a) : "l"(p));
    return a;
}
__device__ __forceinline__ void ldsm4(uint32_t& r0, uint32_t& r1, uint32_t& r2, uint32_t& r3, uint32_t addr) {
    asm volatile("ldmatrix.sync.aligned.m8n8.x4.shared.b16 {%0,%1,%2,%3}, [%4];"
        : "=r"(r0), "=r"(r1), "=r"(r2), "=r"(r3) : "r"(addr));
}
__device__ __forceinline__ void mma16816(float* c, uint32_t a0, uint32_t a1, uint32_t a2, uint32_t a3,
                                         uint32_t b0, uint32_t b1) {
    asm("mma.sync.aligned.m16n8k16.row.col.f32.bf16.bf16.f32 "
        "{%0,%1,%2,%3}, {%4,%5,%6,%7}, {%8,%9}, {%0,%1,%2,%3};"
        : "+f"(c[0]), "+f"(c[1]), "+f"(c[2]), "+f"(c[3])
        : "r"(a0), "r"(a1), "r"(a2), "r"(a3), "r"(b0), "r"(b1));
}
__device__ __forceinline__ void tma3d(uint32_t dst, const CUtensorMap* map,
                                      int c0, int c1, int c2, uint32_t mbar) {
    asm volatile("cp.async.bulk.tensor.3d.shared::cta.global.tile.mbarrier::complete_tx::bytes "
        "[%0], [%1, {%2, %3, %4}], [%5];"
        :: "r"(dst), "l"(map), "r"(c0), "r"(c1), "r"(c2), "r"(mbar) : "memory");
}
#define MBARRIER_INIT(mbar, cnt) \
    asm volatile("mbarrier.init.shared.b64 [%0], %1;" :: "r"((uint32_t)(mbar)), "r"((uint32_t)(cnt)) : "memory")
#define MBARRIER_EXPECT_TX(mbar, bytes) \
    asm volatile("mbarrier.arrive.expect_tx.shared.b64 _, [%0], %1;" :: "r"((uint32_t)(mbar)), "r"((uint32_t)(bytes)) : "memory")
#define MBARRIER_WAIT_PARITY(mbar, par) do { \
    uint32_t _m = (uint32_t)(mbar); uint32_t _p = (uint32_t)(par); \
    asm volatile("{\n\t.reg .pred P1;\n\tWAIT_LOOP_%=:\n\t" \
        "mbarrier.try_wait.parity.acquire.cta.shared::cta.b64 P1, [%0], %1, 0x989680;\n\t" \
        "@P1 bra.uni WAIT_DONE_%=;\n\tbra.uni WAIT_LOOP_%=;\n\tWAIT_DONE_%=:\n\t}" \
        :: "r"(_m), "r"(_p) : "memory"); \
} while (0)

// ---------------- 0) Wg transpose: g_wgt[e][k] = Wg[k][e] ----------------
__global__ void wg_transpose(const float* __restrict__ Wg) {
    int e = blockIdx.x;
    for (int k = threadIdx.x; k < DD; k += 256)
        g_wgt[e * DD + k] = Wg[(size_t)k * EE + e];
}

// ---------------- 1) gate GEMM: tensor-map TMA (SW128), f32x2 over K ------
#define XS_BYTES (128 * 128)             // 16384 per stage (128 rows x 128B)
#define WGS_BYTES (EE * 128)             // 2048 per stage
#define GATE_SM (2 * (XS_BYTES + WGS_BYTES))     // 36864
#define GATE_TX (XS_BYTES + WGS_BYTES)           // 18432 per stage

__global__ void __launch_bounds__(256) gate_kernel(
        const __grid_constant__ CUtensorMap xmap,
        const __grid_constant__ CUtensorMap wgmap,
        const float* __restrict__ bg) {
    extern __shared__ __align__(1024) uint8_t gsm[];
    __shared__ __align__(8) ULL s_mbar[2];
    uint8_t* xs  = gsm;
    uint8_t* wgs = gsm + 2 * XS_BYTES;

    int tid = threadIdx.x;
    int t0 = blockIdx.x * 128;
    int b  = t0 >> 11;
    int s0 = t0 & 2047;

    uint32_t mb[2] = { smem_u32(&s_mbar[0]), smem_u32(&s_mbar[1]) };

    int tx = tid & 7;
    int ty = tid >> 3;
    int e0 = tx * 2;
    int m0 = ty * 4;

    if (tid == 0) { MBARRIER_INIT(mb[0], 1); MBARRIER_INIT(mb[1], 1); }
    __syncthreads();

    ULL acc2[4][2];
    #pragma unroll
    for (int i = 0; i < 4; ++i) { acc2[i][0] = 0ULL; acc2[i][1] = 0ULL; }

    const int nch = DD / 32;

    auto issue = [&](int c) {
        int slot = c & 1;
        int k0 = c * 32;
        if (tid == 0) {
            MBARRIER_EXPECT_TX(mb[slot], GATE_TX);
            tma3d(smem_u32(xs + slot * XS_BYTES), &xmap, k0, s0, b, mb[slot]);
            tma3d(smem_u32(wgs + slot * WGS_BYTES), &wgmap, k0, 0, 0, mb[slot]);
        }
    };

    int ph[2] = {0, 0};
    issue(0);

    for (int c = 0; c < nch; ++c) {
        int slot = c & 1;
        MBARRIER_WAIT_PARITY(mb[slot], ph[slot]);
        ph[slot] ^= 1;
        __syncthreads();
        if (c + 1 < nch) issue(c + 1);

        const uint8_t* xv = xs + slot * XS_BYTES;
        const uint8_t* wv = wgs + slot * WGS_BYTES;

        #pragma unroll
        for (int k4 = 0; k4 < 8; ++k4) {
            ulonglong2 wp0 = *(const ulonglong2*)(wv + (e0 + 0) * 128 + ((k4 * 16) ^ (((e0 + 0) & 7) << 4)));
            ulonglong2 wp1 = *(const ulonglong2*)(wv + (e0 + 1) * 128 + ((k4 * 16) ^ (((e0 + 1) & 7) << 4)));
            #pragma unroll
            for (int i = 0; i < 4; ++i) {
                int r = m0 + i;
                ulonglong2 xp = *(const ulonglong2*)(xv + r * 128 + ((k4 * 16) ^ ((r & 7) << 4)));
                fma2(acc2[i][0], xp.x, wp0.x);
                fma2(acc2[i][0], xp.y, wp0.y);
                fma2(acc2[i][1], xp.x, wp1.x);
                fma2(acc2[i][1], xp.y, wp1.y);
            }
        }
    }

    #pragma unroll
    for (int j = 0; j < 2; ++j) {
        float bb = bg[e0 + j];
        float4 o;
        float2 v0 = unpack2(acc2[0][j]);
        float2 v1 = unpack2(acc2[1][j]);
        float2 v2 = unpack2(acc2[2][j]);
        float2 v3 = unpack2(acc2[3][j]);
        o.x = v0.x + v0.y + bb;
        o.y = v1.x + v1.y + bb;
        o.z = v2.x + v2.y + bb;
        o.w = v3.x + v3.y + bb;
        *(float4*)&g_logits[((size_t)(b * EE) + e0 + j) * SS + s0 + m0] = o;
    }
}

// ---------------- 2) softmax(+top4) + gather (bf16-split output) ----------------
__global__ void topk_gather_kernel(const float* __restrict__ x) {
    int e = blockIdx.x, b = blockIdx.y;
    __shared__ float sv[SS];
    __shared__ float red[256];
    __shared__ int   redi[256];
    __shared__ float s_max, s_sum;
    __shared__ int   s_idx[KK];
    __shared__ float s_val[KK];
    int tid = threadIdx.x;

    const float* row = &g_logits[(size_t)(b * EE + e) * SS];
    float lmax = -FLT_MAX;
    for (int i = tid; i < SS; i += 256) {
        float v = row[i];
        sv[i] = v;
        lmax = fmaxf(lmax, v);
    }
    red[tid] = lmax;
    __syncthreads();
    for (int off = 128; off > 0; off >>= 1) {
        if (tid < off) red[tid] = fmaxf(red[tid], red[tid + off]);
        __syncthreads();
    }
    if (tid == 0) s_max = red[0];
    __syncthreads();
    float mx = s_max;

    float lsum = 0.f;
    for (int i = tid; i < SS; i += 256) lsum += expf(sv[i] - mx);
    red[tid] = lsum;
    __syncthreads();
    for (int off = 128; off > 0; off >>= 1) {
        if (tid < off) red[tid] += red[tid + off];
        __syncthreads();
    }
    if (tid == 0) s_sum = red[0];
    __syncthreads();
    float inv = 1.0f / s_sum;

    for (int it = 0; it < KK; ++it) {
        float bv = -FLT_MAX;
        int bi = SS;
        for (int i = tid; i < SS; i += 256) {
            float v = sv[i];
            if (v > bv) { bv = v; bi = i; }
        }
        red[tid] = bv; redi[tid] = bi;
        __syncthreads();
        for (int off = 128; off > 0; off >>= 1) {
            if (tid < off) {
                float v2 = red[tid + off]; int i2 = redi[tid + off];
                if (v2 > red[tid] || (v2 == red[tid] && i2 < redi[tid])) {
                    red[tid] = v2; redi[tid] = i2;
                }
            }
            __syncthreads();
        }
        if (tid == 0) {
            int wi = redi[0];
            s_idx[it] = wi;
            s_val[it] = expf(red[0] - mx) * inv;
            sv[wi] = -FLT_MAX;
        }
        __syncthreads();
    }

    #pragma unroll
    for (int j = 0; j < KK; ++j) {
        int idx = s_idx[j];
        float w = s_val[j];
        const float4* src = (const float4*)&x[((size_t)b * SS + idx) * DD];
        __nv_bfloat16* dh = &g_inph[((size_t)(e * BB + b)) * KD + j * DD];
        __nv_bfloat16* dl = &g_inpl[((size_t)(e * BB + b)) * KD + j * DD];
        int d4 = tid;
        float4 v = src[d4];
        v.x *= w; v.y *= w; v.z *= w; v.w *= w;
        uint32_t h0, l0, h1, l1;
        split2(v.x, v.y, h0, l0);
        split2(v.z, v.w, h1, l1);
        *(uint2*)&dh[d4 * 4] = make_uint2(h0, h1);
        *(uint2*)&dl[d4 * 4] = make_uint2(l0, l1);
    }
}

// ---------------- 3) expert GEMM1: TMA 2-stage + mma.sync, split-K (R14) ----
#define A_STRIDE 40
#define W_SUB 4096                     // 32 rows * 128B per subtile
#define WS_BYTES (4 * W_SUB)           // 16384 per stage
#define AH_BYTES (32 * A_STRIDE * 2)   // 2560 per stage
#define SM_AH_OFF (2 * WS_BYTES)                  // 32768
#define SM_AL_OFF (SM_AH_OFF + 2 * AH_BYTES)      // 37888
#define SM_TOTAL  (SM_AL_OFF + 2 * AH_BYTES)      // 43008
#define EXP_TX (WS_BYTES + 2 * AH_BYTES)          // 21504 per stage

__global__ void __launch_bounds__(256) expert_mma0(
        const __grid_constant__ CUtensorMap wmap,
        const __grid_constant__ CUtensorMap ahmap,
        const __grid_constant__ CUtensorMap almap,
        int Ktot) {
    extern __shared__ __align__(1024) uint8_t sm[];
    __shared__ __align__(8) ULL s_mbar[2];

    int e = blockIdx.y, nt = blockIdx.x, ks = blockIdx.z;
    const int Ksub = Ktot / SPLIT;
    const int k0base = ks * Ksub;
    const int nch = Ksub >> 5;

    float* P = g_part + ((size_t)(ks * EE + e) * BB) * OO + nt * 128;

    int tid = threadIdx.x, lane = tid & 31, wid = tid >> 5;
    int n0 = wid * 16;

    uint32_t mb[2] = { smem_u32(&s_mbar[0]), smem_u32(&s_mbar[1]) };
    if (tid == 0) { MBARRIER_INIT(mb[0], 1); MBARRIER_INIT(mb[1], 1); }
    __syncthreads();

    float acc[2][2][4];
    #pragma unroll
    for (int mt = 0; mt < 2; ++mt)
        #pragma unroll
        for (int nf = 0; nf < 2; ++nf)
            #pragma unroll
            for (int q = 0; q < 4; ++q) acc[mt][nf][q] = 0.f;

    auto issue = [&](int c) {
        int slot = c & 1;
        int k0 = k0base + c * 32;
        if (tid == 0) {
            MBARRIER_EXPECT_TX(mb[slot], EXP_TX);
            #pragma unroll
            for (int q = 0; q < 4; ++q)
                tma3d(smem_u32(sm + slot * WS_BYTES + q * W_SUB), &wmap,
                      nt * 128 + q * 32, k0, e, mb[slot]);
            tma3d(smem_u32(sm + SM_AH_OFF + slot * AH_BYTES), &ahmap, k0, 0, e, mb[slot]);
            tma3d(smem_u32(sm + SM_AL_OFF + slot * AH_BYTES), &almap, k0, 0, e, mb[slot]);
        }
    };

    int ph[2] = {0, 0};
    issue(0);

    for (int c = 0; c < nch; ++c) {
        int slot = c & 1;
        MBARRIER_WAIT_PARITY(mb[slot], ph[slot]);
        ph[slot] ^= 1;
        __syncthreads();
        if (c + 1 < nch) issue(c + 1);

        const uint8_t* Wb = sm + slot * WS_BYTES;
        uint32_t ah_base = smem_u32(sm + SM_AH_OFF + slot * AH_BYTES) + ((lane & 15) * A_STRIDE + (lane >> 4) * 8) * 2;
        uint32_t al_base = smem_u32(sm + SM_AL_OFF + slot * AH_BYTES) + ((lane & 15) * A_STRIDE + (lane >> 4) * 8) * 2;

        #pragma unroll
        for (int ks2 = 0; ks2 < 2; ++ks2) {
            uint32_t ah0[4], ah1[4], al0[4], al1[4];
            ldsm4(ah0[0], ah0[1], ah0[2], ah0[3], ah_base + ks2 * 32);
            ldsm4(ah1[0], ah1[1], ah1[2], ah1[3], ah_base + ks2 * 32 + 16 * A_STRIDE * 2);
            ldsm4(al0[0], al0[1], al0[2], al0[3], al_base + ks2 * 32);
            ldsm4(al1[0], al1[1], al1[2], al1[3], al_base + ks2 * 32 + 16 * A_STRIDE * 2);
            #pragma unroll
            for (int nf = 0; nf < 2; ++nf) {
                int cc = n0 + nf * 8 + (lane >> 2);
                int q = cc >> 5;
                int c4 = (cc & 31) * 4;
                int kk = ks2 * 16 + (lane & 3) * 2;
                const uint8_t* Wq = Wb + q * W_SUB;
                float f0 = *(const float*)(Wq + (kk + 0) * 128 + (c4 ^ (((kk + 0) & 7) << 4)));
                float f1 = *(const float*)(Wq + (kk + 1) * 128 + (c4 ^ (((kk + 1) & 7) << 4)));
                float f2 = *(const float*)(Wq + (kk + 8) * 128 + (c4 ^ (((kk + 8) & 7) << 4)));
                float f3 = *(const float*)(Wq + (kk + 9) * 128 + (c4 ^ (((kk + 9) & 7) << 4)));
                uint32_t b0h, b0l, b1h, b1l;
                split2(f0, f1, b0h, b0l);
                split2(f2, f3, b1h, b1l);
                mma16816(acc[0][nf], ah0[0], ah0[1], ah0[2], ah0[3], b0h, b1h);
                mma16816(acc[1][nf], ah1[0], ah1[1], ah1[2], ah1[3], b0h, b1h);
                mma16816(acc[0][nf], al0[0], al0[1], al0[2], al0[3], b0h, b1h);
                mma16816(acc[1][nf], al1[0], al1[1], al1[2], al1[3], b0h, b1h);
                mma16816(acc[0][nf], ah0[0], ah0[1], ah0[2], ah0[3], b0l, b1l);
                mma16816(acc[1][nf], ah1[0], ah1[1], ah1[2], ah1[3], b0l, b1l);
            }
        }
    }

    #pragma unroll
    for (int mt = 0; mt < 2; ++mt) {
        int r = mt * 16 + (lane >> 2);
        #pragma unroll
        for (int nf = 0; nf < 2; ++nf) {
            int nc = n0 + nf * 8 + (lane & 3) * 2;
            *(float2*)&P[(size_t)r * OO + nc]       = make_float2(acc[mt][nf][0], acc[mt][nf][1]);
            *(float2*)&P[(size_t)(r + 8) * OO + nc] = make_float2(acc[mt][nf][2], acc[mt][nf][3]);
        }
    }
}

// ---------------- 3b) expert GEMM2/3: no split-K, fused bias(+relu)+split epilogue ----
// 128 threads (4 warps), N-tile 64, grid (16 tiles, 16 experts). K=1024, 32 chunks.
#define W2S_BYTES (2 * W_SUB)          // 8192 per stage (2 subtiles)
#define F_AH_OFF (2 * W2S_BYTES)                  // 16384
#define F_AL_OFF (F_AH_OFF + 2 * AH_BYTES)        // 21504
#define F_SM_TOTAL (F_AL_OFF + 2 * AH_BYTES)      // 26624
#define F_TX (W2S_BYTES + 2 * AH_BYTES)           // 13312 per stage

template<int MODE>   // 1: ->h2 (relu+split), 2: ->out fp32
__global__ void __launch_bounds__(128) expert_mma_fused(
        const __grid_constant__ CUtensorMap wmap,
        const __grid_constant__ CUtensorMap ahmap,
        const __grid_constant__ CUtensorMap almap,
        const float* __restrict__ bias,
        float* __restrict__ outF) {
    extern __shared__ __align__(1024) uint8_t sm[];
    __shared__ __align__(8) ULL s_mbar[2];

    int e = blockIdx.y, nt = blockIdx.x;
    const int nch = OO >> 5;   // 32 chunks

    int tid = threadIdx.x, lane = tid & 31, wid = tid >> 5;
    int n0 = wid * 16;

    uint32_t mb[2] = { smem_u32(&s_mbar[0]), smem_u32(&s_mbar[1]) };
    if (tid == 0) { MBARRIER_INIT(mb[0], 1); MBARRIER_INIT(mb[1], 1); }
    __syncthreads();

    float acc[2][2][4];
    #pragma unroll
    for (int mt = 0; mt < 2; ++mt)
        #pragma unroll
        for (int nf = 0; nf < 2; ++nf)
            #pragma unroll
            for (int q = 0; q < 4; ++q) acc[mt][nf][q] = 0.f;

    auto issue = [&](int c) {
        int slot = c & 1;
        int k0 = c * 32;
        if (tid == 0) {
            MBARRIER_EXPECT_TX(mb[slot], F_TX);
            #pragma unroll
            for (int q = 0; q < 2; ++q)
                tma3d(smem_u32(sm + slot * W2S_BYTES + q * W_SUB), &wmap,
                      nt * 64 + q * 32, k0, e, mb[slot]);
            tma3d(smem_u32(sm + F_AH_OFF + slot * AH_BYTES), &ahmap, k0, 0, e, mb[slot]);
            tma3d(smem_u32(sm + F_AL_OFF + slot * AH_BYTES), &almap, k0, 0, e, mb[slot]);
        }
    };

    int ph[2] = {0, 0};
    issue(0);

    for (int c = 0; c < nch; ++c) {
        int slot = c & 1;
        MBARRIER_WAIT_PARITY(mb[slot], ph[slot]);
        ph[slot] ^= 1;
        __syncthreads();
        if (c + 1 < nch) issue(c + 1);

        const uint8_t* Wb = sm + slot * W2S_BYTES;
        uint32_t ah_base = smem_u32(sm + F_AH_OFF + slot * AH_BYTES) + ((lane & 15) * A_STRIDE + (lane >> 4) * 8) * 2;
        uint32_t al_base = smem_u32(sm + F_AL_OFF + slot * AH_BYTES) + ((lane & 15) * A_STRIDE + (lane >> 4) * 8) * 2;

        #pragma unroll
        for (int ks2 = 0; ks2 < 2; ++ks2) {
            uint32_t ah0[4], ah1[4], al0[4], al1[4];
            ldsm4(ah0[0], ah0[1], ah0[2], ah0[3], ah_base + ks2 * 32);
            ldsm4(ah1[0], ah1[1], ah1[2], ah1[3], ah_base + ks2 * 32 + 16 * A_STRIDE * 2);
            ldsm4(al0[0], al0[1], al0[2], al0[3], al_base + ks2 * 32);
            ldsm4(al1[0], al1[1], al1[2], al1[3], al_base + ks2 * 32 + 16 * A_STRIDE * 2);
            #pragma unroll
            for (int nf = 0; nf < 2; ++nf) {
                int cc = n0 + nf * 8 + (lane >> 2);
                int q = cc >> 5;
                int c4 = (cc & 31) * 4;
                int kk = ks2 * 16 + (lane & 3) * 2;
                const uint8_t* Wq = Wb + q * W_SUB;
                float f0 = *(const float*)(Wq + (kk + 0) * 128 + (c4 ^ (((kk + 0) & 7) << 4)));
                float f1 = *(const float*)(Wq + (kk + 1) * 128 + (c4 ^ (((kk + 1) & 7) << 4)));
                float f2 = *(const float*)(Wq + (kk + 8) * 128 + (c4 ^ (((kk + 8) & 7) << 4)));
                float f3 = *(const float*)(Wq + (kk + 9) * 128 + (c4 ^ (((kk + 9) & 7) << 4)));
                uint32_t b0h, b0l, b1h, b1l;
                split2(f0, f1, b0h, b0l);
                split2(f2, f3, b1h, b1l);
                mma16816(acc[0][nf], ah0[0], ah0[1], ah0[2], ah0[3], b0h, b1h);
                mma16816(acc[1][nf], ah1[0], ah1[1], ah1[2], ah1[3], b0h, b1h);
                mma16816(acc[0][nf], al0[0], al0[1], al0[2], al0[3], b0h, b1h);
                mma16816(acc[1][nf], al1[0], al1[1], al1[2], al1[3], b0h, b1h);
                mma16816(acc[0][nf], ah0[0], ah0[1], ah0[2], ah0[3], b0l, b1l);
                mma16816(acc[1][nf], ah1[0], ah1[1], ah1[2], ah1[3], b0l, b1l);
            }
        }
    }

    // fused epilogue
    #pragma unroll
    for (int mt = 0; mt < 2; ++mt) {
        int r = mt * 16 + (lane >> 2);        // batch row
        #pragma unroll
        for (int nf = 0; nf < 2; ++nf) {
            int nc = nt * 64 + n0 + nf * 8 + (lane & 3) * 2;   // global col
            float bb0 = bias[(size_t)e * OO + nc];
            float bb1 = bias[(size_t)e * OO + nc + 1];
            float v00 = acc[mt][nf][0] + bb0, v01 = acc[mt][nf][1] + bb1;   // row r
            float v10 = acc[mt][nf][2] + bb0, v11 = acc[mt][nf][3] + bb1;   // row r+8
            if (MODE == 1) {
                v00 = fmaxf(v00, 0.f); v01 = fmaxf(v01, 0.f);
                v10 = fmaxf(v10, 0.f); v11 = fmaxf(v11, 0.f);
                uint32_t h0, l0, h1, l1;
                split2(v00, v01, h0, l0);
                split2(v10, v11, h1, l1);
                size_t o0 = ((size_t)(e * BB + r)) * OO + nc;
                size_t o1 = ((size_t)(e * BB + r + 8)) * OO + nc;
                *(uint32_t*)&g_h2h[o0] = h0; *(uint32_t*)&g_h2l[o0] = l0;
                *(uint32_t*)&g_h2h[o1] = h1; *(uint32_t*)&g_h2l[o1] = l1;
            } else {
                *(float2*)&outF[((size_t)r * EE + e) * OO + nc]       = make_float2(v00, v01);
                *(float2*)&outF[((size_t)(r + 8) * EE + e) * OO + nc] = make_float2(v10, v11);
            }
        }
    }
}

// ---------------- 4) split-K reduce for GEMM1 (2 float4 per thread) ----------------
__global__ void reduce_kernel0(const float* __restrict__ bias) {
    int base = blockIdx.x * 512 + threadIdx.x;
    #pragma unroll
    for (int h = 0; h < 2; ++h) {
        int i = base + h * 256;
        int n4 = i & (OO / 4 - 1);
        int m  = (i >> 8) & (BB - 1);
        int e  = i >> 13;

        float4 a = ((const float4*)&g_part[((size_t)e * BB + m) * OO])[n4];
        #pragma unroll
        for (int s = 1; s < SPLIT; ++s) {
            float4 v = ((const float4*)&g_part[((size_t)(s * EE + e) * BB + m) * OO])[n4];
            a.x += v.x; a.y += v.y; a.z += v.z; a.w += v.w;
        }
        float4 bb = ((const float4*)&bias[(size_t)e * OO])[n4];
        a.x += bb.x; a.y += bb.y; a.z += bb.z; a.w += bb.w;
        a.x = fmaxf(a.x, 0.f); a.y = fmaxf(a.y, 0.f);
        a.z = fmaxf(a.z, 0.f); a.w = fmaxf(a.w, 0.f);
        size_t off = ((size_t)(e * BB + m)) * OO + n4 * 4;
        uint32_t h0, l0, h1, l1;
        split2(a.x, a.y, h0, l0);
        split2(a.z, a.w, h1, l1);
        *(uint2*)&g_h1h[off] = make_uint2(h0, h1);
        *(uint2*)&g_h1l[off] = make_uint2(l0, l1);
    }
}

// ---------------- host: tensor map encoding via driver entry point ----------------
typedef CUresult (*PFN_tmEncode)(CUtensorMap*, CUtensorMapDataType, cuuint32_t, void*,
                                 const cuuint64_t*, const cuuint64_t*, const cuuint32_t*,
                                 const cuuint32_t*, CUtensorMapInterleave, CUtensorMapSwizzle,
                                 CUtensorMapL2promotion, CUtensorMapFloatOOBfill);

static void enc3(PFN_tmEncode enc, CUtensorMap* m, void* base, CUtensorMapDataType dt,
                 int elbytes, uint64_t d0, uint64_t d1, uint64_t d2,
                 uint32_t b0, uint32_t b1, CUtensorMapSwizzle sw) {
    cuuint64_t dims[3] = {d0, d1, d2};
    cuuint64_t strides[2] = {d0 * (uint64_t)elbytes, d0 * d1 * (uint64_t)elbytes};
    cuuint32_t box[3] = {b0, b1, 1};
    cuuint32_t es[3] = {1, 1, 1};
    enc(m, dt, 3, base, dims, strides, box, es,
        CU_TENSOR_MAP_INTERLEAVE_NONE, sw,
        CU_TENSOR_MAP_L2_PROMOTION_L2_128B, CU_TENSOR_MAP_FLOAT_OOB_FILL_NONE);
}

extern "C" void kernel_launch(void* const* d_in, const int* in_sizes, int n_in,
                              void* d_out, int out_size) {
    const float* x  = (const float*)d_in[0];
    const float* Wg = (const float*)d_in[1];
    const float* bg = (const float*)d_in[2];
    const float* W1 = (const float*)d_in[3];
    const float* b1 = (const float*)d_in[4];
    const float* W2 = (const float*)d_in[5];
    const float* b2 = (const float*)d_in[6];
    const float* W3 = (const float*)d_in[7];
    const float* b3 = (const float*)d_in[8];
    float* out = (float*)d_out;

    static bool attr_done = false;
    if (!attr_done) {
        cudaFuncSetAttribute(gate_kernel, cudaFuncAttributeMaxDynamicSharedMemorySize, GATE_SM);
        cudaFuncSetAttribute(expert_mma0, cudaFuncAttributeMaxDynamicSharedMemorySize, SM_TOTAL);
        cudaFuncSetAttribute(expert_mma_fused<1>, cudaFuncAttributeMaxDynamicSharedMemorySize, F_SM_TOTAL);
        cudaFuncSetAttribute(expert_mma_fused<2>, cudaFuncAttributeMaxDynamicSharedMemorySize, F_SM_TOTAL);
        attr_done = true;
    }

    PFN_tmEncode enc = nullptr;
    cudaDriverEntryPointQueryResult qr;
    cudaGetDriverEntryPoint("cuTensorMapEncodeTiled", (void**)&enc, cudaEnableDefault, &qr);

    void *p_wgt, *p_inph, *p_inpl, *p_h1h, *p_h1l, *p_h2h, *p_h2l;
    cudaGetSymbolAddress(&p_wgt, g_wgt);
    cudaGetSymbolAddress(&p_inph, g_inph);
    cudaGetSymbolAddress(&p_inpl, g_inpl);
    cudaGetSymbolAddress(&p_h1h, g_h1h);
    cudaGetSymbolAddress(&p_h1l, g_h1l);
    cudaGetSymbolAddress(&p_h2h, g_h2h);
    cudaGetSymbolAddress(&p_h2l, g_h2l);

    const CUtensorMapDataType F32 = CU_TENSOR_MAP_DATA_TYPE_FLOAT32;
    const CUtensorMapDataType BF16 = CU_TENSOR_MAP_DATA_TYPE_BFLOAT16;
    const CUtensorMapSwizzle SW128 = CU_TENSOR_MAP_SWIZZLE_128B;
    const CUtensorMapSwizzle SWN   = CU_TENSOR_MAP_SWIZZLE_NONE;

    CUtensorMap xmap, wgmap;
    enc3(enc, &xmap, (void*)x, F32, 4, DD, SS, BB, 32, 128, SW128);
    enc3(enc, &wgmap, p_wgt, F32, 4, DD, EE, 1, 32, EE, SW128);

    CUtensorMap w1m, w2m, w3m;
    enc3(enc, &w1m, (void*)W1, F32, 4, OO, KD, EE, 32, 32, SW128);
    enc3(enc, &w2m, (void*)W2, F32, 4, OO, OO, EE, 32, 32, SW128);
    enc3(enc, &w3m, (void*)W3, F32, 4, OO, OO, EE, 32, 32, SW128);

    CUtensorMap iph, ipl, h1h, h1l, h2h, h2l;
    enc3(enc, &iph, p_inph, BF16, 2, KD, BB, EE, A_STRIDE, 32, SWN);
    enc3(enc, &ipl, p_inpl, BF16, 2, KD, BB, EE, A_STRIDE, 32, SWN);
    enc3(enc, &h1h, p_h1h, BF16, 2, OO, BB, EE, A_STRIDE, 32, SWN);
    enc3(enc, &h1l, p_h1l, BF16, 2, OO, BB, EE, A_STRIDE, 32, SWN);
    enc3(enc, &h2h, p_h2h, BF16, 2, OO, BB, EE, A_STRIDE, 32, SWN);
    enc3(enc, &h2l, p_h2l, BF16, 2, OO, BB, EE, A_STRIDE, 32, SWN);

    wg_transpose<<<EE, 256>>>(Wg);
    gate_kernel<<<(BB * SS) / 128, 256, GATE_SM>>>(xmap, wgmap, bg);
    topk_gather_kernel<<<dim3(EE, BB), 256>>>(x);

    expert_mma0<<<dim3(OO / 128, EE, SPLIT), 256, SM_TOTAL>>>(w1m, iph, ipl, KD);
    reduce_kernel0<<<(EE * BB * OO / 4) / 512, 256>>>(b1);

    expert_mma_fused<1><<<dim3(OO / 64, EE), 128, F_SM_TOTAL>>>(w2m, h1h, h1l, b2, nullptr);
    expert_mma_fused<2><<<dim3(OO / 64, EE), 128, F_SM_TOTAL>>>(w3m, h2h, h2l, b3, out);
}

// round 16
// speedup vs baseline: 1.1313x; 1.1313x over previous
#include <cuda_runtime.h>
#include <cuda.h>
#include <cuda_bf16.h>
#include <float.h>
#include <cstdint>

// Problem constants
#define BB 32
#define SS 2048
#define DD 1024
#define EE 16
#define KK 4
#define OO 1024
#define KD 4096   // KK*DD
#define SPLIT 4

typedef unsigned long long ULL;

// ---------------- scratch (device globals) ----------------
__device__ float g_logits[BB * EE * SS];            // [B][E][S], 4 MB
__device__ float g_wgt[EE * DD];                    // Wg transposed [e][k], 64 KB
__device__ __nv_bfloat16 g_inph[EE * BB * KD];      // inp hi, [e][b][4096]
__device__ __nv_bfloat16 g_inpl[EE * BB * KD];      // inp lo
__device__ __nv_bfloat16 g_h1h[EE * BB * OO];
__device__ __nv_bfloat16 g_h1l[EE * BB * OO];
__device__ __nv_bfloat16 g_h2h[EE * BB * OO];
__device__ __nv_bfloat16 g_h2l[EE * BB * OO];
__device__ float g_part[SPLIT * EE * BB * OO];      // split-K partials, 8 MB

// ---------------- f32x2 helpers ----------------
__device__ __forceinline__ void fma2(ULL& d, ULL a, ULL b) {
    asm("fma.rn.f32x2 %0, %1, %2, %0;" : "+l"(d) : "l"(a), "l"(b));
}
__device__ __forceinline__ float2 unpack2(ULL v) {
    float2 f; asm("mov.b64 {%0, %1}, %2;" : "=f"(f.x), "=f"(f.y) : "l"(v)); return f;
}

// ---------------- bf16 split helper ----------------
__device__ __forceinline__ void split2(float a, float b, uint32_t& hi, uint32_t& lo) {
    asm("cvt.rn.satfinite.bf16x2.f32 %0, %1, %2;" : "=r"(hi) : "f"(b), "f"(a));
    __nv_bfloat162 hp = *reinterpret_cast<__nv_bfloat162*>(&hi);
    float r0 = a - __low2float(hp);
    float r1 = b - __high2float(hp);
    asm("cvt.rn.satfinite.bf16x2.f32 %0, %1, %2;" : "=r"(lo) : "f"(r1), "f"(r0));
}

// ---------------- portable tensor-core / TMA helpers ----------------
__device__ __forceinline__ uint32_t smem_u32(const void* p) {
    uint32_t a;
    asm("{ .reg .u64 t; cvta.to.shared.u64 t, %1; cvt.u32.u64 %0, t; }" : "=r"(a) : "l"(p));
    return a;
}
__device__ __forceinline__ void ldsm4(uint32_t& r0, uint32_t& r1, uint32_t& r2, uint32_t& r3, uint32_t addr) {
    asm volatile("ldmatrix.sync.aligned.m8n8.x4.shared.b16 {%0,%1,%2,%3}, [%4];"
        : "=r"(r0), "=r"(r1), "=r"(r2), "=r"(r3) : "r"(addr));
}
__device__ __forceinline__ void mma16816(float* c, uint32_t a0, uint32_t a1, uint32_t a2, uint32_t a3,
                                         uint32_t b0, uint32_t b1) {
    asm("mma.sync.aligned.m16n8k16.row.col.f32.bf16.bf16.f32 "
        "{%0,%1,%2,%3}, {%4,%5,%6,%7}, {%8,%9}, {%0,%1,%2,%3};"
        : "+f"(c[0]), "+f"(c[1]), "+f"(c[2]), "+f"(c[3])
        : "r"(a0), "r"(a1), "r"(a2), "r"(a3), "r"(b0), "r"(b1));
}
__device__ __forceinline__ void tma3d(uint32_t dst, const CUtensorMap* map,
                                      int c0, int c1, int c2, uint32_t mbar) {
    asm volatile("cp.async.bulk.tensor.3d.shared::cta.global.tile.mbarrier::complete_tx::bytes "
        "[%0], [%1, {%2, %3, %4}], [%5];"
        :: "r"(dst), "l"(map), "r"(c0), "r"(c1), "r"(c2), "r"(mbar) : "memory");
}
#define MBARRIER_INIT(mbar, cnt) \
    asm volatile("mbarrier.init.shared.b64 [%0], %1;" :: "r"((uint32_t)(mbar)), "r"((uint32_t)(cnt)) : "memory")
#define MBARRIER_EXPECT_TX(mbar, bytes) \
    asm volatile("mbarrier.arrive.expect_tx.shared.b64 _, [%0], %1;" :: "r"((uint32_t)(mbar)), "r"((uint32_t)(bytes)) : "memory")
#define MBARRIER_WAIT_PARITY(mbar, par) do { \
    uint32_t _m = (uint32_t)(mbar); uint32_t _p = (uint32_t)(par); \
    asm volatile("{\n\t.reg .pred P1;\n\tWAIT_LOOP_%=:\n\t" \
        "mbarrier.try_wait.parity.acquire.cta.shared::cta.b64 P1, [%0], %1, 0x989680;\n\t" \
        "@P1 bra.uni WAIT_DONE_%=;\n\tbra.uni WAIT_LOOP_%=;\n\tWAIT_DONE_%=:\n\t}" \
        :: "r"(_m), "r"(_p) : "memory"); \
} while (0)

// ---------------- 0) Wg transpose: g_wgt[e][k] = Wg[k][e] ----------------
__global__ void wg_transpose(const float* __restrict__ Wg) {
    int e = blockIdx.x;
    for (int k = threadIdx.x; k < DD; k += 256)
        g_wgt[e * DD + k] = Wg[(size_t)k * EE + e];
}

// ---------------- 1) gate GEMM: TMA (SW128), f32x2 over K, 256-token CTA ---
// Thread tile: 4 tokens x 4 experts (4 tx-groups -> 4x smem redundancy).
#define XS_BYTES (256 * 128)             // 32768 per stage (256 rows x 128B)
#define WGS_BYTES (EE * 128)             // 2048 per stage
#define GATE_SM (2 * (XS_BYTES + WGS_BYTES))     // 69632
#define GATE_TX (XS_BYTES + WGS_BYTES)           // 34816 per stage

__global__ void __launch_bounds__(256) gate_kernel(
        const __grid_constant__ CUtensorMap xmap,
        const __grid_constant__ CUtensorMap wgmap,
        const float* __restrict__ bg) {
    extern __shared__ __align__(1024) uint8_t gsm[];
    __shared__ __align__(8) ULL s_mbar[2];
    uint8_t* xs  = gsm;                       // [2][256 rows][128B], swizzled
    uint8_t* wgs = gsm + 2 * XS_BYTES;        // [2][16 rows][128B], swizzled

    int tid = threadIdx.x;
    int t0 = blockIdx.x * 256;
    int b  = t0 >> 11;
    int s0 = t0 & 2047;

    uint32_t mb[2] = { smem_u32(&s_mbar[0]), smem_u32(&s_mbar[1]) };

    int tx = tid & 3;                     // expert-group
    int ty = tid >> 2;                    // token-group 0..63
    int e0 = tx * 4;
    int m0 = ty * 4;

    if (tid == 0) { MBARRIER_INIT(mb[0], 1); MBARRIER_INIT(mb[1], 1); }
    __syncthreads();

    ULL acc2[4][4];                       // [token][expert], packed over k-pairs
    #pragma unroll
    for (int i = 0; i < 4; ++i)
        #pragma unroll
        for (int j = 0; j < 4; ++j) acc2[i][j] = 0ULL;

    const int nch = DD / 32;

    auto issue = [&](int c) {
        int slot = c & 1;
        int k0 = c * 32;
        if (tid == 0) {
            MBARRIER_EXPECT_TX(mb[slot], GATE_TX);
            tma3d(smem_u32(xs + slot * XS_BYTES), &xmap, k0, s0, b, mb[slot]);
            tma3d(smem_u32(wgs + slot * WGS_BYTES), &wgmap, k0, 0, 0, mb[slot]);
        }
    };

    int ph[2] = {0, 0};
    issue(0);

    for (int c = 0; c < nch; ++c) {
        int slot = c & 1;
        MBARRIER_WAIT_PARITY(mb[slot], ph[slot]);
        ph[slot] ^= 1;
        __syncthreads();
        if (c + 1 < nch) issue(c + 1);

        const uint8_t* xv = xs + slot * XS_BYTES;
        const uint8_t* wv = wgs + slot * WGS_BYTES;

        #pragma unroll
        for (int k4 = 0; k4 < 8; ++k4) {
            ulonglong2 wp[4];
            #pragma unroll
            for (int j = 0; j < 4; ++j) {
                int e = e0 + j;
                wp[j] = *(const ulonglong2*)(wv + e * 128 + ((k4 * 16) ^ ((e & 7) << 4)));
            }
            #pragma unroll
            for (int i = 0; i < 4; ++i) {
                int r = m0 + i;
                ulonglong2 xp = *(const ulonglong2*)(xv + r * 128 + ((k4 * 16) ^ ((r & 7) << 4)));
                #pragma unroll
                for (int j = 0; j < 4; ++j) {
                    fma2(acc2[i][j], xp.x, wp[j].x);
                    fma2(acc2[i][j], xp.y, wp[j].y);
                }
            }
        }
    }

    // epilogue: horizontal add over k-pairs, + bg, float4 store along S
    #pragma unroll
    for (int j = 0; j < 4; ++j) {
        int e = e0 + j;
        float bb = bg[e];
        float4 o;
        float2 v0 = unpack2(acc2[0][j]);
        float2 v1 = unpack2(acc2[1][j]);
        float2 v2 = unpack2(acc2[2][j]);
        float2 v3 = unpack2(acc2[3][j]);
        o.x = v0.x + v0.y + bb;
        o.y = v1.x + v1.y + bb;
        o.z = v2.x + v2.y + bb;
        o.w = v3.x + v3.y + bb;
        *(float4*)&g_logits[((size_t)(b * EE) + e) * SS + s0 + m0] = o;
    }
}

// ---------------- 2) softmax(+top4) + gather (bf16-split output) ----------------
__global__ void topk_gather_kernel(const float* __restrict__ x) {
    int e = blockIdx.x, b = blockIdx.y;
    __shared__ float sv[SS];
    __shared__ float red[256];
    __shared__ int   redi[256];
    __shared__ float s_max, s_sum;
    __shared__ int   s_idx[KK];
    __shared__ float s_val[KK];
    int tid = threadIdx.x;

    const float* row = &g_logits[(size_t)(b * EE + e) * SS];
    float lmax = -FLT_MAX;
    for (int i = tid; i < SS; i += 256) {
        float v = row[i];
        sv[i] = v;
        lmax = fmaxf(lmax, v);
    }
    red[tid] = lmax;
    __syncthreads();
    for (int off = 128; off > 0; off >>= 1) {
        if (tid < off) red[tid] = fmaxf(red[tid], red[tid + off]);
        __syncthreads();
    }
    if (tid == 0) s_max = red[0];
    __syncthreads();
    float mx = s_max;

    float lsum = 0.f;
    for (int i = tid; i < SS; i += 256) lsum += expf(sv[i] - mx);
    red[tid] = lsum;
    __syncthreads();
    for (int off = 128; off > 0; off >>= 1) {
        if (tid < off) red[tid] += red[tid + off];
        __syncthreads();
    }
    if (tid == 0) s_sum = red[0];
    __syncthreads();
    float inv = 1.0f / s_sum;

    for (int it = 0; it < KK; ++it) {
        float bv = -FLT_MAX;
        int bi = SS;
        for (int i = tid; i < SS; i += 256) {
            float v = sv[i];
            if (v > bv) { bv = v; bi = i; }
        }
        red[tid] = bv; redi[tid] = bi;
        __syncthreads();
        for (int off = 128; off > 0; off >>= 1) {
            if (tid < off) {
                float v2 = red[tid + off]; int i2 = redi[tid + off];
                if (v2 > red[tid] || (v2 == red[tid] && i2 < redi[tid])) {
                    red[tid] = v2; redi[tid] = i2;
                }
            }
            __syncthreads();
        }
        if (tid == 0) {
            int wi = redi[0];
            s_idx[it] = wi;
            s_val[it] = expf(red[0] - mx) * inv;
            sv[wi] = -FLT_MAX;
        }
        __syncthreads();
    }

    #pragma unroll
    for (int j = 0; j < KK; ++j) {
        int idx = s_idx[j];
        float w = s_val[j];
        const float4* src = (const float4*)&x[((size_t)b * SS + idx) * DD];
        __nv_bfloat16* dh = &g_inph[((size_t)(e * BB + b)) * KD + j * DD];
        __nv_bfloat16* dl = &g_inpl[((size_t)(e * BB + b)) * KD + j * DD];
        int d4 = tid;
        float4 v = src[d4];
        v.x *= w; v.y *= w; v.z *= w; v.w *= w;
        uint32_t h0, l0, h1, l1;
        split2(v.x, v.y, h0, l0);
        split2(v.z, v.w, h1, l1);
        *(uint2*)&dh[d4 * 4] = make_uint2(h0, h1);
        *(uint2*)&dl[d4 * 4] = make_uint2(l0, l1);
    }
}

// ---------------- 3) expert GEMM: tensor-map TMA (W SW128 subtiles) ----------
#define A_STRIDE 40
#define W_SUB 4096                     // 32 rows * 128B per subtile
#define WS_BYTES (4 * W_SUB)           // 16384 per stage
#define AH_BYTES (32 * A_STRIDE * 2)   // 2560 per stage
#define SM_AH_OFF (2 * WS_BYTES)                  // 32768
#define SM_AL_OFF (SM_AH_OFF + 2 * AH_BYTES)      // 37888
#define SM_TOTAL  (SM_AL_OFF + 2 * AH_BYTES)      // 43008
#define EXP_TX (WS_BYTES + 2 * AH_BYTES)          // 21504 per stage

template<int MODE>
__global__ void __launch_bounds__(256) expert_mma(
        const __grid_constant__ CUtensorMap wmap,
        const __grid_constant__ CUtensorMap ahmap,
        const __grid_constant__ CUtensorMap almap,
        int Ktot) {
    extern __shared__ __align__(1024) uint8_t sm[];
    __shared__ __align__(8) ULL s_mbar[2];

    int e = blockIdx.y, nt = blockIdx.x, ks = blockIdx.z;
    const int Ksub = Ktot / SPLIT;
    const int k0base = ks * Ksub;
    const int nch = Ksub >> 5;

    float* P = g_part + ((size_t)(ks * EE + e) * BB) * OO + nt * 128;

    int tid = threadIdx.x, lane = tid & 31, wid = tid >> 5;
    int n0 = wid * 16;

    uint32_t mb[2] = { smem_u32(&s_mbar[0]), smem_u32(&s_mbar[1]) };
    if (tid == 0) { MBARRIER_INIT(mb[0], 1); MBARRIER_INIT(mb[1], 1); }
    __syncthreads();

    float acc[2][2][4];
    #pragma unroll
    for (int mt = 0; mt < 2; ++mt)
        #pragma unroll
        for (int nf = 0; nf < 2; ++nf)
            #pragma unroll
            for (int q = 0; q < 4; ++q) acc[mt][nf][q] = 0.f;

    auto issue = [&](int c) {
        int slot = c & 1;
        int k0 = k0base + c * 32;
        if (tid == 0) {
            MBARRIER_EXPECT_TX(mb[slot], EXP_TX);
            #pragma unroll
            for (int q = 0; q < 4; ++q)
                tma3d(smem_u32(sm + slot * WS_BYTES + q * W_SUB), &wmap,
                      nt * 128 + q * 32, k0, e, mb[slot]);
            tma3d(smem_u32(sm + SM_AH_OFF + slot * AH_BYTES), &ahmap, k0, 0, e, mb[slot]);
            tma3d(smem_u32(sm + SM_AL_OFF + slot * AH_BYTES), &almap, k0, 0, e, mb[slot]);
        }
    };

    int ph[2] = {0, 0};
    issue(0);

    for (int c = 0; c < nch; ++c) {
        int slot = c & 1;
        MBARRIER_WAIT_PARITY(mb[slot], ph[slot]);
        ph[slot] ^= 1;
        __syncthreads();
        if (c + 1 < nch) issue(c + 1);

        const uint8_t* Wb = sm + slot * WS_BYTES;
        uint32_t ah_base = smem_u32(sm + SM_AH_OFF + slot * AH_BYTES) + ((lane & 15) * A_STRIDE + (lane >> 4) * 8) * 2;
        uint32_t al_base = smem_u32(sm + SM_AL_OFF + slot * AH_BYTES) + ((lane & 15) * A_STRIDE + (lane >> 4) * 8) * 2;

        #pragma unroll
        for (int ks2 = 0; ks2 < 2; ++ks2) {
            uint32_t ah0[4], ah1[4], al0[4], al1[4];
            ldsm4(ah0[0], ah0[1], ah0[2], ah0[3], ah_base + ks2 * 32);
            ldsm4(ah1[0], ah1[1], ah1[2], ah1[3], ah_base + ks2 * 32 + 16 * A_STRIDE * 2);
            ldsm4(al0[0], al0[1], al0[2], al0[3], al_base + ks2 * 32);
            ldsm4(al1[0], al1[1], al1[2], al1[3], al_base + ks2 * 32 + 16 * A_STRIDE * 2);
            #pragma unroll
            for (int nf = 0; nf < 2; ++nf) {
                int cc = n0 + nf * 8 + (lane >> 2);
                int q = cc >> 5;
                int c4 = (cc & 31) * 4;
                int kk = ks2 * 16 + (lane & 3) * 2;
                const uint8_t* Wq = Wb + q * W_SUB;
                float f0 = *(const float*)(Wq + (kk + 0) * 128 + (c4 ^ (((kk + 0) & 7) << 4)));
                float f1 = *(const float*)(Wq + (kk + 1) * 128 + (c4 ^ (((kk + 1) & 7) << 4)));
                float f2 = *(const float*)(Wq + (kk + 8) * 128 + (c4 ^ (((kk + 8) & 7) << 4)));
                float f3 = *(const float*)(Wq + (kk + 9) * 128 + (c4 ^ (((kk + 9) & 7) << 4)));
                uint32_t b0h, b0l, b1h, b1l;
                split2(f0, f1, b0h, b0l);
                split2(f2, f3, b1h, b1l);
                mma16816(acc[0][nf], ah0[0], ah0[1], ah0[2], ah0[3], b0h, b1h);
                mma16816(acc[1][nf], ah1[0], ah1[1], ah1[2], ah1[3], b0h, b1h);
                mma16816(acc[0][nf], al0[0], al0[1], al0[2], al0[3], b0h, b1h);
                mma16816(acc[1][nf], al1[0], al1[1], al1[2], al1[3], b0h, b1h);
                mma16816(acc[0][nf], ah0[0], ah0[1], ah0[2], ah0[3], b0l, b1l);
                mma16816(acc[1][nf], ah1[0], ah1[1], ah1[2], ah1[3], b0l, b1l);
            }
        }
    }

    #pragma unroll
    for (int mt = 0; mt < 2; ++mt) {
        int r = mt * 16 + (lane >> 2);
        #pragma unroll
        for (int nf = 0; nf < 2; ++nf) {
            int nc = n0 + nf * 8 + (lane & 3) * 2;
            *(float2*)&P[(size_t)r * OO + nc]       = make_float2(acc[mt][nf][0], acc[mt][nf][1]);
            *(float2*)&P[(size_t)(r + 8) * OO + nc] = make_float2(acc[mt][nf][2], acc[mt][nf][3]);
        }
    }
}

// ---------------- 4) split-K reduce (2 float4 per thread) ----------------
template<int MODE>
__global__ void reduce_kernel(const float* __restrict__ bias, float* __restrict__ outF) {
    int base = blockIdx.x * 512 + threadIdx.x;
    #pragma unroll
    for (int h = 0; h < 2; ++h) {
        int i = base + h * 256;
        int n4 = i & (OO / 4 - 1);
        int m  = (i >> 8) & (BB - 1);
        int e  = i >> 13;

        float4 a = ((const float4*)&g_part[((size_t)e * BB + m) * OO])[n4];
        #pragma unroll
        for (int s = 1; s < SPLIT; ++s) {
            float4 v = ((const float4*)&g_part[((size_t)(s * EE + e) * BB + m) * OO])[n4];
            a.x += v.x; a.y += v.y; a.z += v.z; a.w += v.w;
        }
        float4 bb = ((const float4*)&bias[(size_t)e * OO])[n4];
        a.x += bb.x; a.y += bb.y; a.z += bb.z; a.w += bb.w;
        if (MODE < 2) {
            a.x = fmaxf(a.x, 0.f); a.y = fmaxf(a.y, 0.f);
            a.z = fmaxf(a.z, 0.f); a.w = fmaxf(a.w, 0.f);
            __nv_bfloat16* dh = (MODE == 0) ? g_h1h : g_h2h;
            __nv_bfloat16* dl = (MODE == 0) ? g_h1l : g_h2l;
            size_t off = ((size_t)(e * BB + m)) * OO + n4 * 4;
            uint32_t h0, l0, h1, l1;
            split2(a.x, a.y, h0, l0);
            split2(a.z, a.w, h1, l1);
            *(uint2*)&dh[off] = make_uint2(h0, h1);
            *(uint2*)&dl[off] = make_uint2(l0, l1);
        } else {
            ((float4*)&outF[((size_t)m * EE + e) * OO])[n4] = a;
        }
    }
}

// ---------------- host: tensor map encoding via driver entry point ----------------
typedef CUresult (*PFN_tmEncode)(CUtensorMap*, CUtensorMapDataType, cuuint32_t, void*,
                                 const cuuint64_t*, const cuuint64_t*, const cuuint32_t*,
                                 const cuuint32_t*, CUtensorMapInterleave, CUtensorMapSwizzle,
                                 CUtensorMapL2promotion, CUtensorMapFloatOOBfill);

static void enc3(PFN_tmEncode enc, CUtensorMap* m, void* base, CUtensorMapDataType dt,
                 int elbytes, uint64_t d0, uint64_t d1, uint64_t d2,
                 uint32_t b0, uint32_t b1, CUtensorMapSwizzle sw) {
    cuuint64_t dims[3] = {d0, d1, d2};
    cuuint64_t strides[2] = {d0 * (uint64_t)elbytes, d0 * d1 * (uint64_t)elbytes};
    cuuint32_t box[3] = {b0, b1, 1};
    cuuint32_t es[3] = {1, 1, 1};
    enc(m, dt, 3, base, dims, strides, box, es,
        CU_TENSOR_MAP_INTERLEAVE_NONE, sw,
        CU_TENSOR_MAP_L2_PROMOTION_L2_128B, CU_TENSOR_MAP_FLOAT_OOB_FILL_NONE);
}

extern "C" void kernel_launch(void* const* d_in, const int* in_sizes, int n_in,
                              void* d_out, int out_size) {
    const float* x  = (const float*)d_in[0];
    const float* Wg = (const float*)d_in[1];
    const float* bg = (const float*)d_in[2];
    const float* W1 = (const float*)d_in[3];
    const float* b1 = (const float*)d_in[4];
    const float* W2 = (const float*)d_in[5];
    const float* b2 = (const float*)d_in[6];
    const float* W3 = (const float*)d_in[7];
    const float* b3 = (const float*)d_in[8];
    float* out = (float*)d_out;

    static bool attr_done = false;
    if (!attr_done) {
        cudaFuncSetAttribute(gate_kernel, cudaFuncAttributeMaxDynamicSharedMemorySize, GATE_SM);
        cudaFuncSetAttribute(expert_mma<0>, cudaFuncAttributeMaxDynamicSharedMemorySize, SM_TOTAL);
        cudaFuncSetAttribute(expert_mma<1>, cudaFuncAttributeMaxDynamicSharedMemorySize, SM_TOTAL);
        cudaFuncSetAttribute(expert_mma<2>, cudaFuncAttributeMaxDynamicSharedMemorySize, SM_TOTAL);
        attr_done = true;
    }

    PFN_tmEncode enc = nullptr;
    cudaDriverEntryPointQueryResult qr;
    cudaGetDriverEntryPoint("cuTensorMapEncodeTiled", (void**)&enc, cudaEnableDefault, &qr);

    void *p_wgt, *p_inph, *p_inpl, *p_h1h, *p_h1l, *p_h2h, *p_h2l;
    cudaGetSymbolAddress(&p_wgt, g_wgt);
    cudaGetSymbolAddress(&p_inph, g_inph);
    cudaGetSymbolAddress(&p_inpl, g_inpl);
    cudaGetSymbolAddress(&p_h1h, g_h1h);
    cudaGetSymbolAddress(&p_h1l, g_h1l);
    cudaGetSymbolAddress(&p_h2h, g_h2h);
    cudaGetSymbolAddress(&p_h2l, g_h2l);

    const CUtensorMapDataType F32 = CU_TENSOR_MAP_DATA_TYPE_FLOAT32;
    const CUtensorMapDataType BF16 = CU_TENSOR_MAP_DATA_TYPE_BFLOAT16;
    const CUtensorMapSwizzle SW128 = CU_TENSOR_MAP_SWIZZLE_128B;
    const CUtensorMapSwizzle SWN   = CU_TENSOR_MAP_SWIZZLE_NONE;

    CUtensorMap xmap, wgmap;
    enc3(enc, &xmap, (void*)x, F32, 4, DD, SS, BB, 32, 256, SW128);
    enc3(enc, &wgmap, p_wgt, F32, 4, DD, EE, 1, 32, EE, SW128);

    CUtensorMap w1m, w2m, w3m;
    enc3(enc, &w1m, (void*)W1, F32, 4, OO, KD, EE, 32, 32, SW128);
    enc3(enc, &w2m, (void*)W2, F32, 4, OO, OO, EE, 32, 32, SW128);
    enc3(enc, &w3m, (void*)W3, F32, 4, OO, OO, EE, 32, 32, SW128);

    CUtensorMap iph, ipl, h1h, h1l, h2h, h2l;
    enc3(enc, &iph, p_inph, BF16, 2, KD, BB, EE, A_STRIDE, 32, SWN);
    enc3(enc, &ipl, p_inpl, BF16, 2, KD, BB, EE, A_STRIDE, 32, SWN);
    enc3(enc, &h1h, p_h1h, BF16, 2, OO, BB, EE, A_STRIDE, 32, SWN);
    enc3(enc, &h1l, p_h1l, BF16, 2, OO, BB, EE, A_STRIDE, 32, SWN);
    enc3(enc, &h2h, p_h2h, BF16, 2, OO, BB, EE, A_STRIDE, 32, SWN);
    enc3(enc, &h2l, p_h2l, BF16, 2, OO, BB, EE, A_STRIDE, 32, SWN);

    const int RED_GRID = (EE * BB * OO / 4) / 512;   // 256

    wg_transpose<<<EE, 256>>>(Wg);
    gate_kernel<<<(BB * SS) / 256, 256, GATE_SM>>>(xmap, wgmap, bg);
    topk_gather_kernel<<<dim3(EE, BB), 256>>>(x);

    expert_mma<0><<<dim3(OO / 128, EE, SPLIT), 256, SM_TOTAL>>>(w1m, iph, ipl, KD);
    reduce_kernel<0><<<RED_GRID, 256>>>(b1, nullptr);

    expert_mma<1><<<dim3(OO / 128, EE, SPLIT), 256, SM_TOTAL>>>(w2m, h1h, h1l, OO);
    reduce_kernel<1><<<RED_GRID, 256>>>(b2, nullptr);

    expert_mma<2><<<dim3(OO / 128, EE, SPLIT), 256, SM_TOTAL>>>(w3m, h2h, h2l, OO);
    reduce_kernel<2><<<RED_GRID, 256>>>(b3, out);
}